// round 16
// baseline (speedup 1.0000x reference)
#include <cuda_runtime.h>
#include <cuda_fp16.h>
#include <cstdint>
#include <math.h>

#define N_NODES_MAX 100000
#define E_MAX       1600000
#define D1 64
#define D2 32
#define SCAN_B 512
#define NB_MAX 256

// Scratch (no allocations allowed)
__device__ __half g_xh  [(size_t)N_NODES_MAX * D1];
__device__ __half g_aggh[(size_t)N_NODES_MAX * D1];
__device__ __half g_x2th[(size_t)N_NODES_MAX * D2];
__device__ int    g_cnt [N_NODES_MAX];   // zeroed by scan (self-restoring)
__device__ int    g_row [N_NODES_MAX + 1];
__device__ int    g_cur [N_NODES_MAX];
__device__ int    g_csr [E_MAX];
__device__ int    g_agg [NB_MAX];        // lookback publish slots (0 = empty)

// ---------------------------------------------------------------------------
// mma / ldmatrix primitives
__device__ __forceinline__ void ldsm_x4(unsigned& a0, unsigned& a1,
                                        unsigned& a2, unsigned& a3, unsigned addr) {
    asm volatile("ldmatrix.sync.aligned.m8n8.x4.shared.b16 {%0,%1,%2,%3}, [%4];"
                 : "=r"(a0), "=r"(a1), "=r"(a2), "=r"(a3) : "r"(addr));
}
__device__ __forceinline__ void ldsm_x2(unsigned& b0, unsigned& b1, unsigned addr) {
    asm volatile("ldmatrix.sync.aligned.m8n8.x2.shared.b16 {%0,%1}, [%2];"
                 : "=r"(b0), "=r"(b1) : "r"(addr));
}
__device__ __forceinline__ void mma16816(float* c,
                                         unsigned a0, unsigned a1, unsigned a2, unsigned a3,
                                         unsigned b0, unsigned b1) {
    asm volatile("mma.sync.aligned.m16n8k16.row.col.f32.f16.f16.f32 "
                 "{%0,%1,%2,%3}, {%4,%5,%6,%7}, {%8,%9}, {%0,%1,%2,%3};"
                 : "+f"(c[0]), "+f"(c[1]), "+f"(c[2]), "+f"(c[3])
                 : "r"(a0), "r"(a1), "r"(a2), "r"(a3), "r"(b0), "r"(b1));
}
__device__ __forceinline__ unsigned packh2(float a, float b) {
    __half2 h = __floats2half2_rn(a, b);
    return *reinterpret_cast<unsigned*>(&h);
}

// fp16 pairwise-add helpers (HADD2)
__device__ __forceinline__ unsigned hadd2u(unsigned a, unsigned b) {
    __half2 r = __hadd2(*reinterpret_cast<__half2*>(&a), *reinterpret_cast<__half2*>(&b));
    return *reinterpret_cast<unsigned*>(&r);
}
__device__ __forceinline__ uint4 hadd2x4(uint4 a, uint4 b) {
    uint4 r;
    r.x = hadd2u(a.x, b.x); r.y = hadd2u(a.y, b.y);
    r.z = hadd2u(a.z, b.z); r.w = hadd2u(a.w, b.w);
    return r;
}
__device__ __forceinline__ uint2 hadd2x2(uint2 a, uint2 b) {
    uint2 r;
    r.x = hadd2u(a.x, b.x); r.y = hadd2u(a.y, b.y);
    return r;
}

// ---------------------------------------------------------------------------
// conv (fp32->fp16) + degree histogram merged.
__global__ void conv_hist_kernel(const float4* __restrict__ x4,
                                 uint2* __restrict__ xh,
                                 const int* __restrict__ dst,
                                 int* __restrict__ cnt,
                                 int n4, int E) {
    int i = blockIdx.x * blockDim.x + threadIdx.x;
    if (i < n4) {
        float4 v = x4[i];
        __half2 a = __floats2half2_rn(v.x, v.y);
        __half2 b = __floats2half2_rn(v.z, v.w);
        uint2 o;
        o.x = *reinterpret_cast<unsigned int*>(&a);
        o.y = *reinterpret_cast<unsigned int*>(&b);
        xh[i] = o;
    }
    if (i < E) atomicAdd(&cnt[dst[i]], 1);
}

// ---------------------------------------------------------------------------
__global__ void __launch_bounds__(SCAN_B)
scan_kernel(int* __restrict__ cnt, int* __restrict__ row, int* __restrict__ cur,
            int* __restrict__ agg, int N, int E) {
    __shared__ int s[SCAN_B];
    int t = threadIdx.x;
    int b = blockIdx.x;
    int i = b * SCAN_B + t;
    int v = (i < N) ? cnt[i] : 0;
    if (i < N) cnt[i] = 0;
    s[t] = v;
    __syncthreads();
#pragma unroll
    for (int off = 1; off < SCAN_B; off <<= 1) {
        int u = 0;
        if (t >= off) u = s[t - off];
        __syncthreads();
        if (t >= off) s[t] += u;
        __syncthreads();
    }
    int incl = s[t];
    if (t == 0) atomicExch(&agg[b], s[SCAN_B - 1] + 1);

    int acc = 0;
    for (int idx = t; idx < b; idx += SCAN_B) {
        volatile int* p = &agg[idx];
        int a;
        while ((a = *p) == 0) { }
        acc += a - 1;
    }
    __syncthreads();
    s[t] = acc;
    __syncthreads();
#pragma unroll
    for (int off = SCAN_B / 2; off > 0; off >>= 1) {
        if (t < off) s[t] += s[t + off];
        __syncthreads();
    }
    int offset = s[0];
    if (i < N) {
        int r = offset + incl - v;
        row[i] = r;
        cur[i] = r;
    }
    if (i == N) row[N] = E;
}

// ---------------------------------------------------------------------------
// CSR fill, 4 edges per thread (R15 proven form).
__global__ void __launch_bounds__(256)
fill_kernel(const int* __restrict__ src, const int* __restrict__ dst,
            int* __restrict__ cur, int* __restrict__ csr,
            int* __restrict__ agg, int E) {
    int t = blockIdx.x * blockDim.x + threadIdx.x;
    if (t < NB_MAX) agg[t] = 0;

    int base = t * 4;
    if (base + 3 < E) {
        int d0 = dst[base],     d1 = dst[base + 1];
        int d2 = dst[base + 2], d3 = dst[base + 3];
        int u0 = src[base],     u1 = src[base + 1];
        int u2 = src[base + 2], u3 = src[base + 3];
        int p0 = atomicAdd(&cur[d0], 1);
        int p1 = atomicAdd(&cur[d1], 1);
        int p2 = atomicAdd(&cur[d2], 1);
        int p3 = atomicAdd(&cur[d3], 1);
        csr[p0] = u0;
        csr[p1] = u1;
        csr[p2] = u2;
        csr[p3] = u3;
    } else {
        for (int i = base; i < E; i++) {
            int d = dst[i];
            int p = atomicAdd(&cur[d], 1);
            csr[p] = src[i];
        }
    }
}

// ---------------------------------------------------------------------------
__device__ __forceinline__ void acc_h8(float* acc, uint4 v) {
    float2 f;
    f = __half22float2(*reinterpret_cast<__half2*>(&v.x)); acc[0] += f.x; acc[1] += f.y;
    f = __half22float2(*reinterpret_cast<__half2*>(&v.y)); acc[2] += f.x; acc[3] += f.y;
    f = __half22float2(*reinterpret_cast<__half2*>(&v.z)); acc[4] += f.x; acc[5] += f.y;
    f = __half22float2(*reinterpret_cast<__half2*>(&v.w)); acc[6] += f.x; acc[7] += f.y;
}

// Layer-1 gather: 16 threads per node. Two 8-lane half-groups split the edge
// quads (even/odd); each keeps the proven 4-wide loop; shfl_xor combines.
__global__ void __launch_bounds__(512)
gather1_kernel(const __half* __restrict__ xh,
               const int*    __restrict__ csr,
               const int*    __restrict__ row,
               __half*       __restrict__ aggh,
               int N) {
    int lane = threadIdx.x & 7;          // feature chunk (16B)
    int half = (threadIdx.x >> 3) & 1;   // edge-quad parity
    int node = blockIdx.x * 32 + (threadIdx.x >> 4);
    if (node >= N) node = N - 1;

    int beg = row[node], end = row[node + 1];
    int deg = end - beg;
    int nq = deg >> 2;                   // full quads
    const uint4* xh4 = reinterpret_cast<const uint4*>(xh);

    float acc[8];
#pragma unroll
    for (int i = 0; i < 8; i++) acc[i] = 0.f;

    for (int q = half; q < nq; q += 2) {
        int e = beg + q * 4;
        int s0 = csr[e], s1 = csr[e + 1], s2 = csr[e + 2], s3 = csr[e + 3];
        uint4 v0 = xh4[(size_t)s0 * 8 + lane];
        uint4 v1 = xh4[(size_t)s1 * 8 + lane];
        uint4 v2 = xh4[(size_t)s2 * 8 + lane];
        uint4 v3 = xh4[(size_t)s3 * 8 + lane];
        uint4 s01 = hadd2x4(v0, v1);
        uint4 s23 = hadd2x4(v2, v3);
        acc_h8(acc, hadd2x4(s01, s23));
    }
    if (half == 0) {
        for (int e = beg + nq * 4; e < end; e++) {
            uint4 v0 = xh4[(size_t)csr[e] * 8 + lane];
            acc_h8(acc, v0);
        }
    }
    // combine the two half-groups (width-16 xor-8 swap)
#pragma unroll
    for (int i = 0; i < 8; i++)
        acc[i] += __shfl_xor_sync(0xffffffffu, acc[i], 8, 16);

    if (half == 0) {
        float inv = 1.0f / fmaxf((float)deg, 1.0f);
        __half2 h0 = __floats2half2_rn(acc[0] * inv, acc[1] * inv);
        __half2 h1 = __floats2half2_rn(acc[2] * inv, acc[3] * inv);
        __half2 h2 = __floats2half2_rn(acc[4] * inv, acc[5] * inv);
        __half2 h3 = __floats2half2_rn(acc[6] * inv, acc[7] * inv);
        uint4 o;
        o.x = *reinterpret_cast<unsigned int*>(&h0);
        o.y = *reinterpret_cast<unsigned int*>(&h1);
        o.z = *reinterpret_cast<unsigned int*>(&h2);
        o.w = *reinterpret_cast<unsigned int*>(&h3);
        reinterpret_cast<uint4*>(aggh)[(size_t)node * 8 + lane] = o;
    }
}

// ---------------------------------------------------------------------------
// Tensor-core double GEMM: x2t = relu(agg@W1 + b1) @ W2 via mma.m16n8k16.
#define AS_STRIDE 72   // halves; 144B rows -> conflict-free ldmatrix
__global__ void __launch_bounds__(256)
gemm1_kernel(const __half* __restrict__ aggh,
             const float*  __restrict__ W1,
             const float*  __restrict__ b1,
             const float*  __restrict__ W2,
             __half*       __restrict__ x2th,
             int N) {
    __shared__ __half As [128][AS_STRIDE];
    __shared__ __half Bt1[64][AS_STRIDE];
    __shared__ __half Bt2[32][AS_STRIDE];
    __shared__ float  b1s[D1];

    int tid = threadIdx.x;

    for (int i = tid; i < D1 * D1; i += 256) {
        int k = i >> 6, n = i & 63;
        Bt1[n][k] = __float2half(W1[i]);
    }
    for (int i = tid; i < D1 * D2; i += 256) {
        int k = i >> 5, n = i & 31;
        Bt2[n][k] = __float2half(W2[i]);
    }
    if (tid < D1) b1s[tid] = b1[tid];

    for (int i = tid; i < 128 * 8; i += 256) {
        int r = i >> 3, ch = i & 7;
        int node = blockIdx.x * 128 + r;
        if (node >= N) node = N - 1;
        uint4 v = reinterpret_cast<const uint4*>(aggh)[(size_t)node * 8 + ch];
        *reinterpret_cast<uint4*>(&As[r][ch * 8]) = v;
    }
    __syncthreads();

    int w = tid >> 5;
    int lane = tid & 31;
    int l16 = lane & 15;

    unsigned a_base = (unsigned)__cvta_generic_to_shared(
        &As[w * 16 + l16][(lane >> 4) * 8]);
    unsigned b1_base = (unsigned)__cvta_generic_to_shared(
        &Bt1[l16 & 7][(l16 >> 3) * 8]);
    unsigned b2_base = (unsigned)__cvta_generic_to_shared(
        &Bt2[l16 & 7][(l16 >> 3) * 8]);
    const unsigned ROWB = AS_STRIDE * 2;

    float acc2[4][4];
#pragma unroll
    for (int n2 = 0; n2 < 4; n2++)
#pragma unroll
        for (int c = 0; c < 4; c++) acc2[n2][c] = 0.f;

    int qc = (lane & 3) * 2;

#pragma unroll
    for (int q = 0; q < 4; q++) {
        float c0[4] = {0.f, 0.f, 0.f, 0.f};
        float c1[4] = {0.f, 0.f, 0.f, 0.f};
#pragma unroll
        for (int kt = 0; kt < 4; kt++) {
            unsigned a0, a1, a2, a3, b0, b1r;
            ldsm_x4(a0, a1, a2, a3, a_base + kt * 32);
            ldsm_x2(b0, b1r, b1_base + (2 * q) * 8 * ROWB + kt * 32);
            mma16816(c0, a0, a1, a2, a3, b0, b1r);
            ldsm_x2(b0, b1r, b1_base + (2 * q + 1) * 8 * ROWB + kt * 32);
            mma16816(c1, a0, a1, a2, a3, b0, b1r);
        }
        int col = q * 16 + qc;
        float bb0 = b1s[col],     bb1 = b1s[col + 1];
        float bb8 = b1s[col + 8], bb9 = b1s[col + 9];
        unsigned a20 = packh2(fmaxf(c0[0] + bb0, 0.f), fmaxf(c0[1] + bb1, 0.f));
        unsigned a21 = packh2(fmaxf(c0[2] + bb0, 0.f), fmaxf(c0[3] + bb1, 0.f));
        unsigned a22 = packh2(fmaxf(c1[0] + bb8, 0.f), fmaxf(c1[1] + bb9, 0.f));
        unsigned a23 = packh2(fmaxf(c1[2] + bb8, 0.f), fmaxf(c1[3] + bb9, 0.f));
#pragma unroll
        for (int n2 = 0; n2 < 4; n2++) {
            unsigned b0, b1r;
            ldsm_x2(b0, b1r, b2_base + n2 * 8 * ROWB + q * 32);
            mma16816(acc2[n2], a20, a21, a22, a23, b0, b1r);
        }
    }

    int r0 = blockIdx.x * 128 + w * 16 + (lane >> 2);
    int r1 = r0 + 8;
#pragma unroll
    for (int n2 = 0; n2 < 4; n2++) {
        int col = n2 * 8 + qc;
        if (r0 < N) {
            __half2 h = __floats2half2_rn(acc2[n2][0], acc2[n2][1]);
            *reinterpret_cast<__half2*>(x2th + (size_t)r0 * D2 + col) = h;
        }
        if (r1 < N) {
            __half2 h = __floats2half2_rn(acc2[n2][2], acc2[n2][3]);
            *reinterpret_cast<__half2*>(x2th + (size_t)r1 * D2 + col) = h;
        }
    }
}

// ---------------------------------------------------------------------------
// Layer 2 + readout: 16 threads per node with edge-quad split, shfl combine.
__global__ void __launch_bounds__(512)
layer2_kernel(const __half* __restrict__ x2th,
              const int*    __restrict__ csr,
              const int*    __restrict__ row,
              const float*  __restrict__ b2,
              const float*  __restrict__ Wd,
              const float*  __restrict__ bd,
              float*        __restrict__ out,
              int N) {
    __shared__ float bs[D2];
    if (threadIdx.x < D2) bs[threadIdx.x] = b2[threadIdx.x];
    __syncthreads();

    int lane = threadIdx.x & 7;          // 4 features (8B)
    int half = (threadIdx.x >> 3) & 1;
    int node = blockIdx.x * 32 + (threadIdx.x >> 4);
    if (node >= N) node = N - 1;

    int beg = row[node], end = row[node + 1];
    int deg = end - beg;
    int nq = deg >> 2;
    const uint2* x2 = reinterpret_cast<const uint2*>(x2th);

    float a0 = 0.f, a1 = 0.f, a2 = 0.f, a3 = 0.f;
    for (int q = half; q < nq; q += 2) {
        int e = beg + q * 4;
        int s0 = csr[e], s1 = csr[e + 1], s2 = csr[e + 2], s3 = csr[e + 3];
        uint2 v0 = x2[(size_t)s0 * 8 + lane];
        uint2 v1 = x2[(size_t)s1 * 8 + lane];
        uint2 v2 = x2[(size_t)s2 * 8 + lane];
        uint2 v3 = x2[(size_t)s3 * 8 + lane];
        uint2 s01 = hadd2x2(v0, v1);
        uint2 s23 = hadd2x2(v2, v3);
        uint2 s = hadd2x2(s01, s23);
        float2 f;
        f = __half22float2(*reinterpret_cast<__half2*>(&s.x)); a0 += f.x; a1 += f.y;
        f = __half22float2(*reinterpret_cast<__half2*>(&s.y)); a2 += f.x; a3 += f.y;
    }
    if (half == 0) {
        for (int e = beg + nq * 4; e < end; e++) {
            uint2 v0 = x2[(size_t)csr[e] * 8 + lane];
            float2 f;
            f = __half22float2(*reinterpret_cast<__half2*>(&v0.x)); a0 += f.x; a1 += f.y;
            f = __half22float2(*reinterpret_cast<__half2*>(&v0.y)); a2 += f.x; a3 += f.y;
        }
    }
    a0 += __shfl_xor_sync(0xffffffffu, a0, 8, 16);
    a1 += __shfl_xor_sync(0xffffffffu, a1, 8, 16);
    a2 += __shfl_xor_sync(0xffffffffu, a2, 8, 16);
    a3 += __shfl_xor_sync(0xffffffffu, a3, 8, 16);

    if (half == 0) {
        float inv = 1.0f / fmaxf((float)deg, 1.0f);
        int j = lane * 4;
        float h0 = fmaxf(fmaf(a0, inv, bs[j + 0]), 0.f);
        float h1 = fmaxf(fmaf(a1, inv, bs[j + 1]), 0.f);
        float h2 = fmaxf(fmaf(a2, inv, bs[j + 2]), 0.f);
        float h3 = fmaxf(fmaf(a3, inv, bs[j + 3]), 0.f);

        float v = (h0 + h1) + (h2 + h3);
#pragma unroll
        for (int off = 4; off > 0; off >>= 1)
            v += __shfl_down_sync(0xffffffffu, v, off, 8);

        if (lane == 0) {
            float m = v * (1.0f / (float)D2);
            float z = fmaf(m, Wd[0], bd[0]);
            out[node] = 1.0f / (1.0f + expf(-z));
        }
    }
}

// ---------------------------------------------------------------------------
extern "C" void kernel_launch(void* const* d_in, const int* in_sizes, int n_in,
                              void* d_out, int out_size) {
    const float* x   = (const float*)d_in[0];
    const int*   src = (const int*)  d_in[1];
    const int*   dst = (const int*)  d_in[2];
    const float* W1  = (const float*)d_in[3];
    const float* b1  = (const float*)d_in[4];
    const float* W2  = (const float*)d_in[5];
    const float* b2  = (const float*)d_in[6];
    const float* Wd  = (const float*)d_in[7];
    const float* bd  = (const float*)d_in[8];
    float* out = (float*)d_out;

    const int N = in_sizes[0] / D1;
    const int E = in_sizes[1];

    __half *xh, *aggh, *x2th;
    int *cnt, *row, *cur, *csr, *agg;
    cudaGetSymbolAddress((void**)&xh,   g_xh);
    cudaGetSymbolAddress((void**)&aggh, g_aggh);
    cudaGetSymbolAddress((void**)&x2th, g_x2th);
    cudaGetSymbolAddress((void**)&cnt,  g_cnt);
    cudaGetSymbolAddress((void**)&row,  g_row);
    cudaGetSymbolAddress((void**)&cur,  g_cur);
    cudaGetSymbolAddress((void**)&csr,  g_csr);
    cudaGetSymbolAddress((void**)&agg,  g_agg);

    const int nb = (N + SCAN_B - 1) / SCAN_B;
    const int n4 = N * (D1 / 4);
    const int big = (n4 > E) ? n4 : E;

    conv_hist_kernel<<<(big + 255) / 256, 256>>>(
        reinterpret_cast<const float4*>(x), reinterpret_cast<uint2*>(xh),
        dst, cnt, n4, E);
    scan_kernel<<<nb, SCAN_B>>>(cnt, row, cur, agg, N, E);
    {
        int threads4 = (E + 3) / 4;
        fill_kernel<<<(threads4 + 255) / 256, 256>>>(src, dst, cur, csr, agg, E);
    }

    gather1_kernel<<<(N + 31) / 32, 512>>>(xh, csr, row, aggh, N);
    gemm1_kernel<<<(N + 127) / 128, 256>>>(aggh, W1, b1, W2, x2th, N);
    layer2_kernel<<<(N + 31) / 32, 512>>>(x2th, csr, row, b2, Wd, bd, out, N);
}

// round 17
// speedup vs baseline: 1.1162x; 1.1162x over previous
#include <cuda_runtime.h>
#include <cuda_fp16.h>
#include <cstdint>
#include <math.h>

#define N_NODES_MAX 100000
#define E_MAX       1600000
#define D1 64
#define D2 32
#define SCAN_B 512
#define NB_MAX 256

// Scratch (no allocations allowed)
__device__ __half g_xh  [(size_t)N_NODES_MAX * D1];
__device__ __half g_aggh[(size_t)N_NODES_MAX * D1];
__device__ __half g_x2th[(size_t)N_NODES_MAX * D2];
__device__ int    g_cnt [N_NODES_MAX];   // zeroed by scan (self-restoring)
__device__ int    g_row [N_NODES_MAX + 1];
__device__ int    g_cur [N_NODES_MAX];
__device__ int    g_csr [E_MAX];
__device__ int    g_agg [NB_MAX];        // lookback publish slots (0 = empty)

// ---------------------------------------------------------------------------
// mma / ldmatrix primitives
__device__ __forceinline__ void ldsm_x4(unsigned& a0, unsigned& a1,
                                        unsigned& a2, unsigned& a3, unsigned addr) {
    asm volatile("ldmatrix.sync.aligned.m8n8.x4.shared.b16 {%0,%1,%2,%3}, [%4];"
                 : "=r"(a0), "=r"(a1), "=r"(a2), "=r"(a3) : "r"(addr));
}
__device__ __forceinline__ void ldsm_x2(unsigned& b0, unsigned& b1, unsigned addr) {
    asm volatile("ldmatrix.sync.aligned.m8n8.x2.shared.b16 {%0,%1}, [%2];"
                 : "=r"(b0), "=r"(b1) : "r"(addr));
}
__device__ __forceinline__ void mma16816(float* c,
                                         unsigned a0, unsigned a1, unsigned a2, unsigned a3,
                                         unsigned b0, unsigned b1) {
    asm volatile("mma.sync.aligned.m16n8k16.row.col.f32.f16.f16.f32 "
                 "{%0,%1,%2,%3}, {%4,%5,%6,%7}, {%8,%9}, {%0,%1,%2,%3};"
                 : "+f"(c[0]), "+f"(c[1]), "+f"(c[2]), "+f"(c[3])
                 : "r"(a0), "r"(a1), "r"(a2), "r"(a3), "r"(b0), "r"(b1));
}
__device__ __forceinline__ unsigned packh2(float a, float b) {
    __half2 h = __floats2half2_rn(a, b);
    return *reinterpret_cast<unsigned*>(&h);
}

// fp16 pairwise-add helpers (HADD2)
__device__ __forceinline__ unsigned hadd2u(unsigned a, unsigned b) {
    __half2 r = __hadd2(*reinterpret_cast<__half2*>(&a), *reinterpret_cast<__half2*>(&b));
    return *reinterpret_cast<unsigned*>(&r);
}
__device__ __forceinline__ uint4 hadd2x4(uint4 a, uint4 b) {
    uint4 r;
    r.x = hadd2u(a.x, b.x); r.y = hadd2u(a.y, b.y);
    r.z = hadd2u(a.z, b.z); r.w = hadd2u(a.w, b.w);
    return r;
}
__device__ __forceinline__ uint2 hadd2x2(uint2 a, uint2 b) {
    uint2 r;
    r.x = hadd2u(a.x, b.x); r.y = hadd2u(a.y, b.y);
    return r;
}

// ---------------------------------------------------------------------------
// conv (fp32->fp16) + degree histogram merged.
__global__ void conv_hist_kernel(const float4* __restrict__ x4,
                                 uint2* __restrict__ xh,
                                 const int* __restrict__ dst,
                                 int* __restrict__ cnt,
                                 int n4, int E) {
    int i = blockIdx.x * blockDim.x + threadIdx.x;
    if (i < n4) {
        float4 v = x4[i];
        __half2 a = __floats2half2_rn(v.x, v.y);
        __half2 b = __floats2half2_rn(v.z, v.w);
        uint2 o;
        o.x = *reinterpret_cast<unsigned int*>(&a);
        o.y = *reinterpret_cast<unsigned int*>(&b);
        xh[i] = o;
    }
    if (i < E) atomicAdd(&cnt[dst[i]], 1);
}

// ---------------------------------------------------------------------------
__global__ void __launch_bounds__(SCAN_B)
scan_kernel(int* __restrict__ cnt, int* __restrict__ row, int* __restrict__ cur,
            int* __restrict__ agg, int N, int E) {
    __shared__ int s[SCAN_B];
    int t = threadIdx.x;
    int b = blockIdx.x;
    int i = b * SCAN_B + t;
    int v = (i < N) ? cnt[i] : 0;
    if (i < N) cnt[i] = 0;
    s[t] = v;
    __syncthreads();
#pragma unroll
    for (int off = 1; off < SCAN_B; off <<= 1) {
        int u = 0;
        if (t >= off) u = s[t - off];
        __syncthreads();
        if (t >= off) s[t] += u;
        __syncthreads();
    }
    int incl = s[t];
    if (t == 0) atomicExch(&agg[b], s[SCAN_B - 1] + 1);

    int acc = 0;
    for (int idx = t; idx < b; idx += SCAN_B) {
        volatile int* p = &agg[idx];
        int a;
        while ((a = *p) == 0) { }
        acc += a - 1;
    }
    __syncthreads();
    s[t] = acc;
    __syncthreads();
#pragma unroll
    for (int off = SCAN_B / 2; off > 0; off >>= 1) {
        if (t < off) s[t] += s[t + off];
        __syncthreads();
    }
    int offset = s[0];
    if (i < N) {
        int r = offset + incl - v;
        row[i] = r;
        cur[i] = r;
    }
    if (i == N) row[N] = E;
}

// ---------------------------------------------------------------------------
// CSR fill, 4 edges per thread (R15 proven form).
__global__ void __launch_bounds__(256)
fill_kernel(const int* __restrict__ src, const int* __restrict__ dst,
            int* __restrict__ cur, int* __restrict__ csr,
            int* __restrict__ agg, int E) {
    int t = blockIdx.x * blockDim.x + threadIdx.x;
    if (t < NB_MAX) agg[t] = 0;

    int base = t * 4;
    if (base + 3 < E) {
        int d0 = dst[base],     d1 = dst[base + 1];
        int d2 = dst[base + 2], d3 = dst[base + 3];
        int u0 = src[base],     u1 = src[base + 1];
        int u2 = src[base + 2], u3 = src[base + 3];
        int p0 = atomicAdd(&cur[d0], 1);
        int p1 = atomicAdd(&cur[d1], 1);
        int p2 = atomicAdd(&cur[d2], 1);
        int p3 = atomicAdd(&cur[d3], 1);
        csr[p0] = u0;
        csr[p1] = u1;
        csr[p2] = u2;
        csr[p3] = u3;
    } else {
        for (int i = base; i < E; i++) {
            int d = dst[i];
            int p = atomicAdd(&cur[d], 1);
            csr[p] = src[i];
        }
    }
}

// ---------------------------------------------------------------------------
__device__ __forceinline__ void acc_h8(float* acc, uint4 v) {
    float2 f;
    f = __half22float2(*reinterpret_cast<__half2*>(&v.x)); acc[0] += f.x; acc[1] += f.y;
    f = __half22float2(*reinterpret_cast<__half2*>(&v.y)); acc[2] += f.x; acc[3] += f.y;
    f = __half22float2(*reinterpret_cast<__half2*>(&v.z)); acc[4] += f.x; acc[5] += f.y;
    f = __half22float2(*reinterpret_cast<__half2*>(&v.w)); acc[6] += f.x; acc[7] += f.y;
}

// Layer-1 gather (R15 shape + index software pipelining): 8 lanes/node,
// 4-wide, next quad's csr indices prefetched while features are in flight.
__global__ void __launch_bounds__(512)
gather1_kernel(const __half* __restrict__ xh,
               const int*    __restrict__ csr,
               const int*    __restrict__ row,
               __half*       __restrict__ aggh,
               int N) {
    int grp = threadIdx.x >> 3;
    int lane = threadIdx.x & 7;
    int node = blockIdx.x * 64 + grp;
    if (node >= N) node = N - 1;

    int beg = row[node], end = row[node + 1];
    const uint4* xh4 = reinterpret_cast<const uint4*>(xh);

    float acc[8];
#pragma unroll
    for (int i = 0; i < 8; i++) acc[i] = 0.f;

    int e = beg;
    int s0 = 0, s1 = 0, s2 = 0, s3 = 0;
    if (e + 3 < end) {
        s0 = csr[e]; s1 = csr[e + 1]; s2 = csr[e + 2]; s3 = csr[e + 3];
    }
    while (e + 3 < end) {
        int c0 = s0, c1 = s1, c2 = s2, c3 = s3;
        int en = e + 4;
        if (en + 3 < end) {   // prefetch next quad indices (overlaps feature loads)
            s0 = csr[en]; s1 = csr[en + 1]; s2 = csr[en + 2]; s3 = csr[en + 3];
        }
        uint4 v0 = xh4[(size_t)c0 * 8 + lane];
        uint4 v1 = xh4[(size_t)c1 * 8 + lane];
        uint4 v2 = xh4[(size_t)c2 * 8 + lane];
        uint4 v3 = xh4[(size_t)c3 * 8 + lane];
        uint4 t01 = hadd2x4(v0, v1);
        uint4 t23 = hadd2x4(v2, v3);
        acc_h8(acc, hadd2x4(t01, t23));
        e = en;
    }
    for (; e < end; e++) {
        uint4 v0 = xh4[(size_t)csr[e] * 8 + lane];
        acc_h8(acc, v0);
    }
    float inv = 1.0f / fmaxf((float)(end - beg), 1.0f);
    __half2 h0 = __floats2half2_rn(acc[0] * inv, acc[1] * inv);
    __half2 h1 = __floats2half2_rn(acc[2] * inv, acc[3] * inv);
    __half2 h2 = __floats2half2_rn(acc[4] * inv, acc[5] * inv);
    __half2 h3 = __floats2half2_rn(acc[6] * inv, acc[7] * inv);
    uint4 o;
    o.x = *reinterpret_cast<unsigned int*>(&h0);
    o.y = *reinterpret_cast<unsigned int*>(&h1);
    o.z = *reinterpret_cast<unsigned int*>(&h2);
    o.w = *reinterpret_cast<unsigned int*>(&h3);
    reinterpret_cast<uint4*>(aggh)[(size_t)node * 8 + lane] = o;
}

// ---------------------------------------------------------------------------
// Tensor-core double GEMM: x2t = relu(agg@W1 + b1) @ W2 via mma.m16n8k16.
#define AS_STRIDE 72   // halves; 144B rows -> conflict-free ldmatrix
__global__ void __launch_bounds__(256)
gemm1_kernel(const __half* __restrict__ aggh,
             const float*  __restrict__ W1,
             const float*  __restrict__ b1,
             const float*  __restrict__ W2,
             __half*       __restrict__ x2th,
             int N) {
    __shared__ __half As [128][AS_STRIDE];
    __shared__ __half Bt1[64][AS_STRIDE];
    __shared__ __half Bt2[32][AS_STRIDE];
    __shared__ float  b1s[D1];

    int tid = threadIdx.x;

    for (int i = tid; i < D1 * D1; i += 256) {
        int k = i >> 6, n = i & 63;
        Bt1[n][k] = __float2half(W1[i]);
    }
    for (int i = tid; i < D1 * D2; i += 256) {
        int k = i >> 5, n = i & 31;
        Bt2[n][k] = __float2half(W2[i]);
    }
    if (tid < D1) b1s[tid] = b1[tid];

    for (int i = tid; i < 128 * 8; i += 256) {
        int r = i >> 3, ch = i & 7;
        int node = blockIdx.x * 128 + r;
        if (node >= N) node = N - 1;
        uint4 v = reinterpret_cast<const uint4*>(aggh)[(size_t)node * 8 + ch];
        *reinterpret_cast<uint4*>(&As[r][ch * 8]) = v;
    }
    __syncthreads();

    int w = tid >> 5;
    int lane = tid & 31;
    int l16 = lane & 15;

    unsigned a_base = (unsigned)__cvta_generic_to_shared(
        &As[w * 16 + l16][(lane >> 4) * 8]);
    unsigned b1_base = (unsigned)__cvta_generic_to_shared(
        &Bt1[l16 & 7][(l16 >> 3) * 8]);
    unsigned b2_base = (unsigned)__cvta_generic_to_shared(
        &Bt2[l16 & 7][(l16 >> 3) * 8]);
    const unsigned ROWB = AS_STRIDE * 2;

    float acc2[4][4];
#pragma unroll
    for (int n2 = 0; n2 < 4; n2++)
#pragma unroll
        for (int c = 0; c < 4; c++) acc2[n2][c] = 0.f;

    int qc = (lane & 3) * 2;

#pragma unroll
    for (int q = 0; q < 4; q++) {
        float c0[4] = {0.f, 0.f, 0.f, 0.f};
        float c1[4] = {0.f, 0.f, 0.f, 0.f};
#pragma unroll
        for (int kt = 0; kt < 4; kt++) {
            unsigned a0, a1, a2, a3, b0, b1r;
            ldsm_x4(a0, a1, a2, a3, a_base + kt * 32);
            ldsm_x2(b0, b1r, b1_base + (2 * q) * 8 * ROWB + kt * 32);
            mma16816(c0, a0, a1, a2, a3, b0, b1r);
            ldsm_x2(b0, b1r, b1_base + (2 * q + 1) * 8 * ROWB + kt * 32);
            mma16816(c1, a0, a1, a2, a3, b0, b1r);
        }
        int col = q * 16 + qc;
        float bb0 = b1s[col],     bb1 = b1s[col + 1];
        float bb8 = b1s[col + 8], bb9 = b1s[col + 9];
        unsigned a20 = packh2(fmaxf(c0[0] + bb0, 0.f), fmaxf(c0[1] + bb1, 0.f));
        unsigned a21 = packh2(fmaxf(c0[2] + bb0, 0.f), fmaxf(c0[3] + bb1, 0.f));
        unsigned a22 = packh2(fmaxf(c1[0] + bb8, 0.f), fmaxf(c1[1] + bb9, 0.f));
        unsigned a23 = packh2(fmaxf(c1[2] + bb8, 0.f), fmaxf(c1[3] + bb9, 0.f));
#pragma unroll
        for (int n2 = 0; n2 < 4; n2++) {
            unsigned b0, b1r;
            ldsm_x2(b0, b1r, b2_base + n2 * 8 * ROWB + q * 32);
            mma16816(acc2[n2], a20, a21, a22, a23, b0, b1r);
        }
    }

    int r0 = blockIdx.x * 128 + w * 16 + (lane >> 2);
    int r1 = r0 + 8;
#pragma unroll
    for (int n2 = 0; n2 < 4; n2++) {
        int col = n2 * 8 + qc;
        if (r0 < N) {
            __half2 h = __floats2half2_rn(acc2[n2][0], acc2[n2][1]);
            *reinterpret_cast<__half2*>(x2th + (size_t)r0 * D2 + col) = h;
        }
        if (r1 < N) {
            __half2 h = __floats2half2_rn(acc2[n2][2], acc2[n2][3]);
            *reinterpret_cast<__half2*>(x2th + (size_t)r1 * D2 + col) = h;
        }
    }
}

// ---------------------------------------------------------------------------
// Layer 2 + readout (R15 shape + index software pipelining).
__global__ void __launch_bounds__(512)
layer2_kernel(const __half* __restrict__ x2th,
              const int*    __restrict__ csr,
              const int*    __restrict__ row,
              const float*  __restrict__ b2,
              const float*  __restrict__ Wd,
              const float*  __restrict__ bd,
              float*        __restrict__ out,
              int N) {
    __shared__ float bs[D2];
    if (threadIdx.x < D2) bs[threadIdx.x] = b2[threadIdx.x];
    __syncthreads();

    int grp = threadIdx.x >> 3;
    int lane = threadIdx.x & 7;
    int node = blockIdx.x * 64 + grp;
    if (node >= N) node = N - 1;

    int beg = row[node], end = row[node + 1];
    const uint2* x2 = reinterpret_cast<const uint2*>(x2th);

    float a0 = 0.f, a1 = 0.f, a2 = 0.f, a3 = 0.f;
    int e = beg;
    int s0 = 0, s1 = 0, s2 = 0, s3 = 0;
    if (e + 3 < end) {
        s0 = csr[e]; s1 = csr[e + 1]; s2 = csr[e + 2]; s3 = csr[e + 3];
    }
    while (e + 3 < end) {
        int c0 = s0, c1 = s1, c2 = s2, c3 = s3;
        int en = e + 4;
        if (en + 3 < end) {
            s0 = csr[en]; s1 = csr[en + 1]; s2 = csr[en + 2]; s3 = csr[en + 3];
        }
        uint2 v0 = x2[(size_t)c0 * 8 + lane];
        uint2 v1 = x2[(size_t)c1 * 8 + lane];
        uint2 v2 = x2[(size_t)c2 * 8 + lane];
        uint2 v3 = x2[(size_t)c3 * 8 + lane];
        uint2 t01 = hadd2x2(v0, v1);
        uint2 t23 = hadd2x2(v2, v3);
        uint2 s = hadd2x2(t01, t23);
        float2 f;
        f = __half22float2(*reinterpret_cast<__half2*>(&s.x)); a0 += f.x; a1 += f.y;
        f = __half22float2(*reinterpret_cast<__half2*>(&s.y)); a2 += f.x; a3 += f.y;
        e = en;
    }
    for (; e < end; e++) {
        uint2 v0 = x2[(size_t)csr[e] * 8 + lane];
        float2 f;
        f = __half22float2(*reinterpret_cast<__half2*>(&v0.x)); a0 += f.x; a1 += f.y;
        f = __half22float2(*reinterpret_cast<__half2*>(&v0.y)); a2 += f.x; a3 += f.y;
    }
    float inv = 1.0f / fmaxf((float)(end - beg), 1.0f);
    int j = lane * 4;
    float h0 = fmaxf(fmaf(a0, inv, bs[j + 0]), 0.f);
    float h1 = fmaxf(fmaf(a1, inv, bs[j + 1]), 0.f);
    float h2 = fmaxf(fmaf(a2, inv, bs[j + 2]), 0.f);
    float h3 = fmaxf(fmaf(a3, inv, bs[j + 3]), 0.f);

    float v = (h0 + h1) + (h2 + h3);
#pragma unroll
    for (int off = 4; off > 0; off >>= 1)
        v += __shfl_down_sync(0xffffffffu, v, off, 8);

    if (lane == 0) {
        float m = v * (1.0f / (float)D2);
        float z = fmaf(m, Wd[0], bd[0]);
        out[node] = 1.0f / (1.0f + expf(-z));
    }
}

// ---------------------------------------------------------------------------
extern "C" void kernel_launch(void* const* d_in, const int* in_sizes, int n_in,
                              void* d_out, int out_size) {
    const float* x   = (const float*)d_in[0];
    const int*   src = (const int*)  d_in[1];
    const int*   dst = (const int*)  d_in[2];
    const float* W1  = (const float*)d_in[3];
    const float* b1  = (const float*)d_in[4];
    const float* W2  = (const float*)d_in[5];
    const float* b2  = (const float*)d_in[6];
    const float* Wd  = (const float*)d_in[7];
    const float* bd  = (const float*)d_in[8];
    float* out = (float*)d_out;

    const int N = in_sizes[0] / D1;
    const int E = in_sizes[1];

    __half *xh, *aggh, *x2th;
    int *cnt, *row, *cur, *csr, *agg;
    cudaGetSymbolAddress((void**)&xh,   g_xh);
    cudaGetSymbolAddress((void**)&aggh, g_aggh);
    cudaGetSymbolAddress((void**)&x2th, g_x2th);
    cudaGetSymbolAddress((void**)&cnt,  g_cnt);
    cudaGetSymbolAddress((void**)&row,  g_row);
    cudaGetSymbolAddress((void**)&cur,  g_cur);
    cudaGetSymbolAddress((void**)&csr,  g_csr);
    cudaGetSymbolAddress((void**)&agg,  g_agg);

    const int nb = (N + SCAN_B - 1) / SCAN_B;
    const int n4 = N * (D1 / 4);
    const int big = (n4 > E) ? n4 : E;

    conv_hist_kernel<<<(big + 255) / 256, 256>>>(
        reinterpret_cast<const float4*>(x), reinterpret_cast<uint2*>(xh),
        dst, cnt, n4, E);
    scan_kernel<<<nb, SCAN_B>>>(cnt, row, cur, agg, N, E);
    {
        int threads4 = (E + 3) / 4;
        fill_kernel<<<(threads4 + 255) / 256, 256>>>(src, dst, cur, csr, agg, E);
    }

    gather1_kernel<<<(N + 63) / 64, 512>>>(xh, csr, row, aggh, N);
    gemm1_kernel<<<(N + 127) / 128, 256>>>(aggh, W1, b1, W2, x2th, N);
    layer2_kernel<<<(N + 63) / 64, 512>>>(x2th, csr, row, b2, Wd, bd, out, N);
}